// round 13
// baseline (speedup 1.0000x reference)
#include <cuda_runtime.h>
#include <cuda_fp16.h>

// Triline interpolation, fp16 SMEM tables, channel-split for 2 CTAs/SM.
//   out[b, :] = lerp(x_line, cx) + lerp(y_line, cy) + lerp(z_line, cz)
// B = 1M, C = 64, N = 512.
//
// Each CTA holds ONE 32-channel half of all three tables in fp16:
// 3 x 512 x 32 x 2B = 96 KB  ->  2 CTAs/SM  ->  64 warps/SM.
// 4 lanes per point (16 B per lane per row), distance-1 coords prefetch.

#define N_ROWS  512
#define C_CH    64
#define CHALF   32
#define NCHUNK  148
#define BLOCK   1024
#define PTS_IT  (BLOCK / 4)                       // 256 points per CTA-iteration
#define TBL_HALVES (N_ROWS * CHALF)               // 16384 halves per table-half
#define SMEM_BYTES (3 * TBL_HALVES * 2)           // 96 KB

struct H8 { __half2 a, b, c, d; };

__device__ __forceinline__ H8 lds_h8(const __half* base, int halfOff) {
    uint4 u = *(const uint4*)(base + halfOff);
    H8 r;
    r.a = *(__half2*)&u.x;  r.b = *(__half2*)&u.y;
    r.c = *(__half2*)&u.z;  r.d = *(__half2*)&u.w;
    return r;
}

__global__ __launch_bounds__(BLOCK, 2) void triline_h16s_kernel(
    const float* __restrict__ coords,   // [B, 3]
    const float* __restrict__ x_line,   // [N, C] fp32
    const float* __restrict__ y_line,
    const float* __restrict__ z_line,
    const float* __restrict__ grid,     // [N]
    float* __restrict__ out,            // [B, C] fp32
    int B, int ptsPer)
{
    extern __shared__ __half smh[];     // [3][512][32]
    __half* sx = smh;
    __half* sy = smh + TBL_HALVES;
    __half* sz = smh + 2 * TBL_HALVES;

    const int tIn   = threadIdx.x;
    const int half  = blockIdx.x & 1;          // channel half: 0 or 1
    const int chunk = blockIdx.x >> 1;         // point chunk: 0..147
    const int choff = half * CHALF;

    // ---- Stage this channel-half of all three tables, fp32 -> fp16 ----
    // 16384 halves / 4 per item = 4096 items; row = 8 float4 per 32-ch half.
    for (int i = tIn; i < TBL_HALVES / 4; i += BLOCK) {
        const int row = i >> 3;
        const int q   = (i & 7) << 2;
        const int src = row * C_CH + choff + q;
        float4 vx = *(const float4*)(x_line + src);
        float4 vy = *(const float4*)(y_line + src);
        float4 vz = *(const float4*)(z_line + src);
        ((__half2*)sx)[2 * i]     = __floats2half2_rn(vx.x, vx.y);
        ((__half2*)sx)[2 * i + 1] = __floats2half2_rn(vx.z, vx.w);
        ((__half2*)sy)[2 * i]     = __floats2half2_rn(vy.x, vy.y);
        ((__half2*)sy)[2 * i + 1] = __floats2half2_rn(vy.z, vy.w);
        ((__half2*)sz)[2 * i]     = __floats2half2_rn(vz.x, vz.y);
        ((__half2*)sz)[2 * i + 1] = __floats2half2_rn(vz.z, vz.w);
    }

    const float g0    = __ldg(grid);
    const float invdx = 1.0f / (__ldg(grid + 1) - g0);

    __syncthreads();

    const int hoff   = (tIn & 3) << 3;         // half-channel offset within the half
    const int pstart = chunk * ptsPer;
    const int pend   = min(pstart + ptsPer, B);

    int p = pstart + (tIn >> 2);
    if (p >= pend) return;

    // ---- Prologue: indices/weights for the first point ----
    int ix, iy, iz;  float wx, wy, wz;
    {
        const float cx = __ldg(coords + 3 * p + 0);
        const float cy = __ldg(coords + 3 * p + 1);
        const float cz = __ldg(coords + 3 * p + 2);
        const float px = (cx - g0) * invdx;
        const float py = (cy - g0) * invdx;
        const float pz = (cz - g0) * invdx;
        ix = min(max(__float2int_rd(px), 0), N_ROWS - 2);
        iy = min(max(__float2int_rd(py), 0), N_ROWS - 2);
        iz = min(max(__float2int_rd(pz), 0), N_ROWS - 2);
        wx = px - (float)ix;  wy = py - (float)iy;  wz = pz - (float)iz;
    }

    for (; p < pend; ) {
        // ---- Issue this point's 6 gathers immediately (addresses ready) ----
        const H8 X0 = lds_h8(sx, (ix << 5) + hoff);
        const H8 X1 = lds_h8(sx, ((ix + 1) << 5) + hoff);
        const H8 Y0 = lds_h8(sy, (iy << 5) + hoff);
        const H8 Y1 = lds_h8(sy, ((iy + 1) << 5) + hoff);
        const H8 Z0 = lds_h8(sz, (iz << 5) + hoff);
        const H8 Z1 = lds_h8(sz, ((iz + 1) << 5) + hoff);

        const __half2 wx2 = __float2half2_rn(wx);
        const __half2 wy2 = __float2half2_rn(wy);
        const __half2 wz2 = __float2half2_rn(wz);

        // ---- Prefetch next point's coords + index math (fills LDS shadow) ----
        const int pn = p + PTS_IT;
        const int pl = (pn < pend) ? pn : p;
        const float cx = __ldg(coords + 3 * pl + 0);
        const float cy = __ldg(coords + 3 * pl + 1);
        const float cz = __ldg(coords + 3 * pl + 2);
        const float px = (cx - g0) * invdx;
        const float py = (cy - g0) * invdx;
        const float pz = (cz - g0) * invdx;
        const int nix = min(max(__float2int_rd(px), 0), N_ROWS - 2);
        const int niy = min(max(__float2int_rd(py), 0), N_ROWS - 2);
        const int niz = min(max(__float2int_rd(pz), 0), N_ROWS - 2);
        const float nwx = px - (float)nix;
        const float nwy = py - (float)niy;
        const float nwz = pz - (float)niz;

        // ---- Consume: fp16 lerp per line, fp32 cross-line sum ----
        __half2 lxa = __hfma2(wx2, __hsub2(X1.a, X0.a), X0.a);
        __half2 lxb = __hfma2(wx2, __hsub2(X1.b, X0.b), X0.b);
        __half2 lxc = __hfma2(wx2, __hsub2(X1.c, X0.c), X0.c);
        __half2 lxd = __hfma2(wx2, __hsub2(X1.d, X0.d), X0.d);
        __half2 lya = __hfma2(wy2, __hsub2(Y1.a, Y0.a), Y0.a);
        __half2 lyb = __hfma2(wy2, __hsub2(Y1.b, Y0.b), Y0.b);
        __half2 lyc = __hfma2(wy2, __hsub2(Y1.c, Y0.c), Y0.c);
        __half2 lyd = __hfma2(wy2, __hsub2(Y1.d, Y0.d), Y0.d);
        __half2 lza = __hfma2(wz2, __hsub2(Z1.a, Z0.a), Z0.a);
        __half2 lzb = __hfma2(wz2, __hsub2(Z1.b, Z0.b), Z0.b);
        __half2 lzc = __hfma2(wz2, __hsub2(Z1.c, Z0.c), Z0.c);
        __half2 lzd = __hfma2(wz2, __hsub2(Z1.d, Z0.d), Z0.d);

        const float2 fa = __half22float2(lxa), ga = __half22float2(lya), ha = __half22float2(lza);
        const float2 fb = __half22float2(lxb), gb = __half22float2(lyb), hb = __half22float2(lzb);
        const float2 fc = __half22float2(lxc), gc = __half22float2(lyc), hc = __half22float2(lzc);
        const float2 fd = __half22float2(lxd), gd = __half22float2(lyd), hd = __half22float2(lzd);

        float4 r0, r1;
        r0.x = fa.x + ga.x + ha.x;  r0.y = fa.y + ga.y + ha.y;
        r0.z = fb.x + gb.x + hb.x;  r0.w = fb.y + gb.y + hb.y;
        r1.x = fc.x + gc.x + hc.x;  r1.y = fc.y + gc.y + hc.y;
        r1.z = fd.x + gd.x + hd.x;  r1.w = fd.y + gd.y + hd.y;

        float* o = out + (size_t)p * C_CH + choff + hoff;
        *(float4*)o       = r0;
        *(float4*)(o + 4) = r1;

        // ---- Rotate pipeline state ----
        p = pn;
        ix = nix; iy = niy; iz = niz;
        wx = nwx; wy = nwy; wz = nwz;
    }
}

extern "C" void kernel_launch(void* const* d_in, const int* in_sizes, int n_in,
                              void* d_out, int out_size)
{
    const float* coords = (const float*)d_in[0];
    const float* x_line = (const float*)d_in[1];
    const float* y_line = (const float*)d_in[2];
    const float* z_line = (const float*)d_in[3];
    const float* grid   = (const float*)d_in[4];
    float* out = (float*)d_out;

    const int B = in_sizes[0] / 3;                 // 1048576
    const int ptsPer = (B + NCHUNK - 1) / NCHUNK;  // 7086

    static int smem_set = 0;
    if (!smem_set) {
        cudaFuncSetAttribute(triline_h16s_kernel,
                             cudaFuncAttributeMaxDynamicSharedMemorySize, SMEM_BYTES);
        smem_set = 1;
    }

    triline_h16s_kernel<<<2 * NCHUNK, BLOCK, SMEM_BYTES>>>(
        coords, x_line, y_line, z_line, grid, out, B, ptsPer);
}

// round 15
// speedup vs baseline: 1.0113x; 1.0113x over previous
#include <cuda_runtime.h>
#include <cuda_fp16.h>

// Triline interpolation, fp16 (base,diff)-packed SMEM tables.
//   out[b, :] = lerp(x_line, cx) + lerp(y_line, cy) + lerp(z_line, cz)
// B = 1M, C = 64, N = 512.
//
// Key trick: lerp = base + w * diff with diff precomputed at staging time.
// Each SMEM entry is half2(base, diff), so one row read per table per point
// (3 LDS.128 instead of 6). Each CTA owns a 32-channel half of all three
// tables: 3 x 512 x 32 x 4 B = 192 KB -> 1 CTA/SM, rows are 128 B ->
// conflict-free LDS.128 (8 lanes x 16 B).

#define N_ROWS  512
#define C_CH    64
#define CHALF   32
#define NCHUNK  148
#define BLOCK   1024
#define PTS_IT  (BLOCK / 8)                       // 128 points per CTA-iteration
#define TBL_H2  (N_ROWS * CHALF)                  // 16384 half2 per table
#define SMEM_BYTES (3 * TBL_H2 * 4)               // 192 KB

__global__ __launch_bounds__(BLOCK, 1) void triline_bd_kernel(
    const float* __restrict__ coords,   // [B, 3]
    const float* __restrict__ x_line,   // [N, C] fp32
    const float* __restrict__ y_line,
    const float* __restrict__ z_line,
    const float* __restrict__ grid,     // [N]
    float* __restrict__ out,            // [B, C] fp32
    int B, int ptsPer)
{
    extern __shared__ __half2 smh2[];   // [3][512][32] of (base, diff)
    __half2* sx = smh2;
    __half2* sy = smh2 + TBL_H2;
    __half2* sz = smh2 + 2 * TBL_H2;

    const int tIn   = threadIdx.x;
    const int half  = blockIdx.x & 1;          // channel half: 0 or 1
    const int chunk = blockIdx.x >> 1;         // point chunk: 0..147
    const int choff = half * CHALF;

    // ---- Stage (base, diff) for this channel-half of all three tables ----
    // Item = 4 channels of one row: 512 * 8 = 4096 items per table.
    for (int i = tIn; i < N_ROWS * 8; i += BLOCK) {
        const int row  = i >> 3;
        const int q    = (i & 7) << 2;
        const int rown = min(row + 1, N_ROWS - 1);
        const int s0   = row  * C_CH + choff + q;
        const int s1   = rown * C_CH + choff + q;

        const float4 x0 = *(const float4*)(x_line + s0);
        const float4 x1 = *(const float4*)(x_line + s1);
        const float4 y0 = *(const float4*)(y_line + s0);
        const float4 y1 = *(const float4*)(y_line + s1);
        const float4 z0 = *(const float4*)(z_line + s0);
        const float4 z1 = *(const float4*)(z_line + s1);

        const int d = row * CHALF + q;
        sx[d + 0] = __floats2half2_rn(x0.x, x1.x - x0.x);
        sx[d + 1] = __floats2half2_rn(x0.y, x1.y - x0.y);
        sx[d + 2] = __floats2half2_rn(x0.z, x1.z - x0.z);
        sx[d + 3] = __floats2half2_rn(x0.w, x1.w - x0.w);
        sy[d + 0] = __floats2half2_rn(y0.x, y1.x - y0.x);
        sy[d + 1] = __floats2half2_rn(y0.y, y1.y - y0.y);
        sy[d + 2] = __floats2half2_rn(y0.z, y1.z - y0.z);
        sy[d + 3] = __floats2half2_rn(y0.w, y1.w - y0.w);
        sz[d + 0] = __floats2half2_rn(z0.x, z1.x - z0.x);
        sz[d + 1] = __floats2half2_rn(z0.y, z1.y - z0.y);
        sz[d + 2] = __floats2half2_rn(z0.z, z1.z - z0.z);
        sz[d + 3] = __floats2half2_rn(z0.w, z1.w - z0.w);
    }

    const float g0    = __ldg(grid);
    const float invdx = 1.0f / (__ldg(grid + 1) - g0);

    __syncthreads();

    const int hq     = (tIn & 7) << 2;         // half2 offset within the 32-ch row
    const int pstart = chunk * ptsPer;
    const int pend   = min(pstart + ptsPer, B);

    int p = pstart + (tIn >> 3);
    if (p >= pend) return;

    // ---- Prologue: indices/weights for the first point ----
    int ix, iy, iz;  float wx, wy, wz;
    {
        const float cx = __ldg(coords + 3 * p + 0);
        const float cy = __ldg(coords + 3 * p + 1);
        const float cz = __ldg(coords + 3 * p + 2);
        const float px = (cx - g0) * invdx;
        const float py = (cy - g0) * invdx;
        const float pz = (cz - g0) * invdx;
        ix = min(max(__float2int_rd(px), 0), N_ROWS - 2);
        iy = min(max(__float2int_rd(py), 0), N_ROWS - 2);
        iz = min(max(__float2int_rd(pz), 0), N_ROWS - 2);
        wx = px - (float)ix;  wy = py - (float)iy;  wz = pz - (float)iz;
    }

    for (; p < pend; ) {
        // ---- 3 conflict-free LDS.128: 4 channels of (base, diff) per table ----
        const uint4 ux = *(const uint4*)(sx + ix * CHALF + hq);
        const uint4 uy = *(const uint4*)(sy + iy * CHALF + hq);
        const uint4 uz = *(const uint4*)(sz + iz * CHALF + hq);

        // ---- Prefetch next point's coords + index math (fills LDS shadow) ----
        const int pn = p + PTS_IT;
        const int pl = (pn < pend) ? pn : p;
        const float cx = __ldg(coords + 3 * pl + 0);
        const float cy = __ldg(coords + 3 * pl + 1);
        const float cz = __ldg(coords + 3 * pl + 2);
        const float px = (cx - g0) * invdx;
        const float py = (cy - g0) * invdx;
        const float pz = (cz - g0) * invdx;
        const int nix = min(max(__float2int_rd(px), 0), N_ROWS - 2);
        const int niy = min(max(__float2int_rd(py), 0), N_ROWS - 2);
        const int niz = min(max(__float2int_rd(pz), 0), N_ROWS - 2);
        const float nwx = px - (float)nix;
        const float nwy = py - (float)niy;
        const float nwz = pz - (float)niz;

        // ---- Consume: per channel fp32 fma of base + w * diff, sum 3 lines ----
        const float2 xa = __half22float2(*(const __half2*)&ux.x);
        const float2 xb = __half22float2(*(const __half2*)&ux.y);
        const float2 xc = __half22float2(*(const __half2*)&ux.z);
        const float2 xd = __half22float2(*(const __half2*)&ux.w);
        const float2 ya = __half22float2(*(const __half2*)&uy.x);
        const float2 yb = __half22float2(*(const __half2*)&uy.y);
        const float2 yc = __half22float2(*(const __half2*)&uy.z);
        const float2 yd = __half22float2(*(const __half2*)&uy.w);
        const float2 za = __half22float2(*(const __half2*)&uz.x);
        const float2 zb = __half22float2(*(const __half2*)&uz.y);
        const float2 zc = __half22float2(*(const __half2*)&uz.z);
        const float2 zd = __half22float2(*(const __half2*)&uz.w);

        float4 r;
        r.x = fmaf(wx, xa.y, xa.x) + fmaf(wy, ya.y, ya.x) + fmaf(wz, za.y, za.x);
        r.y = fmaf(wx, xb.y, xb.x) + fmaf(wy, yb.y, yb.x) + fmaf(wz, zb.y, zb.x);
        r.z = fmaf(wx, xc.y, xc.x) + fmaf(wy, yc.y, yc.x) + fmaf(wz, zc.y, zc.x);
        r.w = fmaf(wx, xd.y, xd.x) + fmaf(wy, yd.y, yd.x) + fmaf(wz, zd.y, zd.x);

        *(float4*)(out + (size_t)p * C_CH + choff + hq) = r;

        // ---- Rotate pipeline state ----
        p = pn;
        ix = nix; iy = niy; iz = niz;
        wx = nwx; wy = nwy; wz = nwz;
    }
}

extern "C" void kernel_launch(void* const* d_in, const int* in_sizes, int n_in,
                              void* d_out, int out_size)
{
    const float* coords = (const float*)d_in[0];
    const float* x_line = (const float*)d_in[1];
    const float* y_line = (const float*)d_in[2];
    const float* z_line = (const float*)d_in[3];
    const float* grid   = (const float*)d_in[4];
    float* out = (float*)d_out;

    const int B = in_sizes[0] / 3;                 // 1048576
    const int ptsPer = (B + NCHUNK - 1) / NCHUNK;  // 7086

    static int smem_set = 0;
    if (!smem_set) {
        cudaFuncSetAttribute(triline_bd_kernel,
                             cudaFuncAttributeMaxDynamicSharedMemorySize, SMEM_BYTES);
        smem_set = 1;
    }

    triline_bd_kernel<<<2 * NCHUNK, BLOCK, SMEM_BYTES>>>(
        coords, x_line, y_line, z_line, grid, out, B, ptsPer);
}